// round 11
// baseline (speedup 1.0000x reference)
#include <cuda_runtime.h>
#include <cuda_fp16.h>
#include <cstdint>
#include <stdint.h>
#include <math.h>

#define N_NODES 8192
#define K_NB    32
#define D_DIM   128
#define H_DIM   256
#define NPB     2          // nodes per block -> M = 64 rows
#define THREADS 512

typedef unsigned int       u32;
typedef unsigned long long u64;

__device__ float g_P[N_NODES * H_DIM];   // x @ W1[:128] + b1
__device__ float g_Q[N_NODES * H_DIM];   // x @ W1[128:]
// W2^T single-fp16 swizzled smem image: row n (512B = 256 k), 128KB
__device__ __align__(16) unsigned char g_W2h[131072];

// ---------------- helpers ----------------
__device__ __forceinline__ u32 smem_u32(const void* p) {
    return (u32)__cvta_generic_to_shared(p);
}
__device__ __forceinline__ void cp_async16(u32 saddr, const void* gaddr) {
    asm volatile("cp.async.cg.shared.global [%0], [%1], 16;" :: "r"(saddr), "l"(gaddr));
}
__device__ __forceinline__ void cp_commit() { asm volatile("cp.async.commit_group;"); }
__device__ __forceinline__ void cp_wait0() {
    asm volatile("cp.async.wait_group 0;" ::: "memory");
}
__device__ __forceinline__ void ldsm4(u32* r, u32 addr) {
    asm volatile("ldmatrix.sync.aligned.m8n8.x4.shared.b16 {%0,%1,%2,%3}, [%4];"
                 : "=r"(r[0]), "=r"(r[1]), "=r"(r[2]), "=r"(r[3]) : "r"(addr));
}
__device__ __forceinline__ void mma_f16(float* c, const u32* a, const u32* b) {
    asm volatile(
        "mma.sync.aligned.m16n8k16.row.col.f32.f16.f16.f32 "
        "{%0,%1,%2,%3}, {%4,%5,%6,%7}, {%8,%9}, {%0,%1,%2,%3};"
        : "+f"(c[0]), "+f"(c[1]), "+f"(c[2]), "+f"(c[3])
        : "r"(a[0]), "r"(a[1]), "r"(a[2]), "r"(a[3]), "r"(b[0]), "r"(b[1]));
}

// ---------------------------------------------------------------------------
__global__ void zero_kernel(float4* __restrict__ out, int n4) {
    int stride = gridDim.x * blockDim.x;
    float4 z = make_float4(0.f, 0.f, 0.f, 0.f);
    for (int i = blockIdx.x * blockDim.x + threadIdx.x; i < n4; i += stride)
        out[i] = z;
}

// ---------------------------------------------------------------------------
#define ROWS_PER_BLK 16
__global__ __launch_bounds__(256) void pq_kernel(
    const float* __restrict__ x, const float* __restrict__ W1,
    const float* __restrict__ b1)
{
    __shared__ float xs[ROWS_PER_BLK * D_DIM];
    const int t = threadIdx.x;
    const int row0 = blockIdx.x * ROWS_PER_BLK;

    const float4* xsrc = (const float4*)(x + (size_t)row0 * D_DIM);
    float4* xdst = (float4*)xs;
    #pragma unroll
    for (int i = 0; i < (ROWS_PER_BLK * D_DIM / 4) / 256; i++)
        xdst[t + i * 256] = xsrc[t + i * 256];
    __syncthreads();

    float accP[ROWS_PER_BLK], accQ[ROWS_PER_BLK];
    #pragma unroll
    for (int r = 0; r < ROWS_PER_BLK; r++) { accP[r] = 0.f; accQ[r] = 0.f; }

    #pragma unroll 4
    for (int d = 0; d < D_DIM; d++) {
        float wp = W1[d * H_DIM + t];
        float wq = W1[(D_DIM + d) * H_DIM + t];
        #pragma unroll
        for (int r = 0; r < ROWS_PER_BLK; r++) {
            float xv = xs[r * D_DIM + d];
            accP[r] = fmaf(xv, wp, accP[r]);
            accQ[r] = fmaf(xv, wq, accQ[r]);
        }
    }
    float bb = b1[t];
    #pragma unroll
    for (int r = 0; r < ROWS_PER_BLK; r++) {
        g_P[(size_t)(row0 + r) * H_DIM + t] = accP[r] + bb;
        g_Q[(size_t)(row0 + r) * H_DIM + t] = accQ[r];
    }
}

// ---------------------------------------------------------------------------
// W2 -> fp16 image of W2^T: row n (0..255, 512B = 256 k fp16), 16B chunks
// XOR-swizzled by (n&7)<<4.
// ---------------------------------------------------------------------------
__global__ void w2prep_kernel(const float* __restrict__ W2) {
    const int k = blockIdx.x;      // 0..255
    const int n = threadIdx.x;     // 0..255
    float v = W2[k * H_DIM + n];
    __half h = __float2half(v);
    u32 off = (u32)(n * 512 + k * 2) ^ (u32)((n & 7) << 4);
    *(__half*)&g_W2h[off] = h;
}

// ---------------------------------------------------------------------------
// Main kernel: 4096 blocks x 512 threads (16 warps), 2 nodes -> M=64.
// smem: W2 fp16 full (128KB) + h1 hi (32KB) + h1 lo (32KB) = 192KB.
// Warp tile 16x64: warp&3 -> 16-row M-group, warp>>2 -> 64-col N-quarter.
// 2-term fp16 (c = a_hi*b + a_lo*b), separate accumulators per term.
// 16 warps/SM (4/SMSP) for latency coverage; K-loop has no syncs.
// ---------------------------------------------------------------------------
#define SMEM_DYN (131072 + 65536)

__global__ __launch_bounds__(THREADS, 1) void mlp_kernel(
    const int* __restrict__ nbrs,
    const float* __restrict__ t_arr, const float* __restrict__ e_hat,
    const float* __restrict__ b2, const float* __restrict__ W3,
    const float* __restrict__ b3, const float* __restrict__ b_scal,
    float* __restrict__ ypred, float* __restrict__ pairwise)
{
    extern __shared__ __align__(128) unsigned char dsm[];
    unsigned char* w2s_p  = dsm;             // 128KB
    unsigned char* h1hi_p = dsm + 131072;    // 32KB
    unsigned char* h1lo_p = dsm + 163840;    // 32KB
    __shared__ float red_s[4][64];
    __shared__ int   cjs_s[64];
    __shared__ float b2s[H_DIM], w3s[H_DIM];

    const int tid  = threadIdx.x;
    const int lane = tid & 31;
    const int warp = tid >> 5;

    if (tid < H_DIM) { b2s[tid] = b2[tid]; w3s[tid] = W3[tid]; }
    if (tid < 64)
        cjs_s[tid] = nbrs[(blockIdx.x * NPB + (tid >> 5)) * (K_NB + 1) + 1 + (tid & 31)];

    const u32 w2sa = smem_u32(w2s_p);
    const u32 h1hi = smem_u32(h1hi_p);
    const u32 h1lo = smem_u32(h1lo_p);

    // load full W2 image (128KB; 256B per thread)
    #pragma unroll
    for (int t = 0; t < 16; t++) {
        int idx = (t * THREADS + tid) * 16;
        cp_async16(w2sa + idx, g_W2h + idx);
    }
    cp_commit();
    __syncthreads();   // cjs_s, b2s, w3s visible

    // ---- build h1 (hi/lo fp16, swizzled): thread -> row tid/8, k-eighth tid&7
    {
        const int mrow = tid >> 3, et = tid & 7;
        const int node_m = blockIdx.x * NPB + (mrow >> 5);
        const int cjm = cjs_s[mrow];
        const float4* Qp = (const float4*)(g_Q + (size_t)cjm    * H_DIM) + et * 8;
        const float4* Pp = (const float4*)(g_P + (size_t)node_m * H_DIM) + et * 8;
        const u32 h1base = (u32)(mrow * 512);
        const u32 swm    = (u32)((mrow & 7) << 4);
        #pragma unroll
        for (int g8 = 0; g8 < 4; g8++) {
            float4 q0 = Qp[g8 * 2], q1 = Qp[g8 * 2 + 1];
            float4 p0 = Pp[g8 * 2], p1 = Pp[g8 * 2 + 1];
            float v0 = fmaxf(p0.x + q0.x, 0.f), v1 = fmaxf(p0.y + q0.y, 0.f);
            float v2 = fmaxf(p0.z + q0.z, 0.f), v3 = fmaxf(p0.w + q0.w, 0.f);
            float v4 = fmaxf(p1.x + q1.x, 0.f), v5 = fmaxf(p1.y + q1.y, 0.f);
            float v6 = fmaxf(p1.z + q1.z, 0.f), v7 = fmaxf(p1.w + q1.w, 0.f);
            __half2 h01 = __floats2half2_rn(v0, v1);
            __half2 h23 = __floats2half2_rn(v2, v3);
            __half2 h45 = __floats2half2_rn(v4, v5);
            __half2 h67 = __floats2half2_rn(v6, v7);
            __half2 l01 = __floats2half2_rn(v0 - __half2float(h01.x),
                                            v1 - __half2float(h01.y));
            __half2 l23 = __floats2half2_rn(v2 - __half2float(h23.x),
                                            v3 - __half2float(h23.y));
            __half2 l45 = __floats2half2_rn(v4 - __half2float(h45.x),
                                            v5 - __half2float(h45.y));
            __half2 l67 = __floats2half2_rn(v6 - __half2float(h67.x),
                                            v7 - __half2float(h67.y));
            uint4 hi4, lo4;
            hi4.x = *(u32*)&h01; hi4.y = *(u32*)&h23;
            hi4.z = *(u32*)&h45; hi4.w = *(u32*)&h67;
            lo4.x = *(u32*)&l01; lo4.y = *(u32*)&l23;
            lo4.z = *(u32*)&l45; lo4.w = *(u32*)&l67;
            u32 off = (h1base + (u32)((et * 4 + g8) * 16)) ^ swm;
            *(uint4*)(h1hi_p + off) = hi4;
            *(uint4*)(h1lo_p + off) = lo4;
        }
    }

    // ---- MMA geometry: warp&3 -> 16-row M-group, warp>>2 -> 64-col N-quarter
    const int m_base = (warp & 3) * 16;
    const int n_base = (warp >> 2) * 64;
    const int kbA = (lane >> 4) * 8;
    const int nB7  = (lane & 7) + ((lane >> 4) & 1) * 8;
    const int kkB7 = ((lane >> 3) & 1) * 8;
    const int tig  = lane & 3;
    const int mA0 = m_base + ((lane >> 3) & 1) * 8 + (lane & 7);
    const u32 aswz = (u32)((mA0 & 7) << 4);

    float ccH[32], ccL[32];
    #pragma unroll
    for (int i = 0; i < 32; i++) { ccH[i] = 0.f; ccL[i] = 0.f; }

    cp_wait0();
    __syncthreads();   // h1 + W2 visible

    #pragma unroll 4
    for (int kt = 0; kt < 16; kt++) {
        u32 ah[4], al[4], bv[4][4];
        u32 offA = ((u32)(mA0 * 512 + (kt * 16 + kbA) * 2)) ^ aswz;
        ldsm4(ah, h1hi + offA);
        ldsm4(al, h1lo + offA);
        #pragma unroll
        for (int fb = 0; fb < 4; fb++) {
            int nB = n_base + fb * 16 + nB7;
            u32 offB = ((u32)(nB * 512 + (kt * 16 + kkB7) * 2)) ^ (u32)((nB & 7) << 4);
            ldsm4(bv[fb], w2sa + offB);
        }
        // 8 hi-term MMAs (independent), then 8 lo-term MMAs (independent)
        #pragma unroll
        for (int fb = 0; fb < 4; fb++) {
            mma_f16(ccH + (2 * fb) * 4,     ah, bv[fb]);
            mma_f16(ccH + (2 * fb + 1) * 4, ah, bv[fb] + 2);
        }
        #pragma unroll
        for (int fb = 0; fb < 4; fb++) {
            mma_f16(ccL + (2 * fb) * 4,     al, bv[fb]);
            mma_f16(ccL + (2 * fb + 1) * 4, al, bv[fb] + 2);
        }
    }

    // ---- epilogue: fold relu(C + b2) . W3 per row (C = ccH + ccL)
    {
        float a0 = 0.f, a1 = 0.f;   // rows m_base + lane/4 and +8
        #pragma unroll
        for (int fn = 0; fn < 8; fn++) {
            int col = n_base + fn * 8 + 2 * tig;
            float b0 = b2s[col], b1v = b2s[col + 1];
            float w0 = w3s[col], w1v = w3s[col + 1];
            const int ci = fn * 4;
            float c0 = ccH[ci + 0] + ccL[ci + 0];
            float c1 = ccH[ci + 1] + ccL[ci + 1];
            float c2 = ccH[ci + 2] + ccL[ci + 2];
            float c3 = ccH[ci + 3] + ccL[ci + 3];
            a0 += fmaf(fmaxf(c0 + b0, 0.f), w0, fmaxf(c1 + b1v, 0.f) * w1v);
            a1 += fmaf(fmaxf(c2 + b0, 0.f), w0, fmaxf(c3 + b1v, 0.f) * w1v);
        }
        a0 += __shfl_xor_sync(0xffffffffu, a0, 1);
        a0 += __shfl_xor_sync(0xffffffffu, a0, 2);
        a1 += __shfl_xor_sync(0xffffffffu, a1, 1);
        a1 += __shfl_xor_sync(0xffffffffu, a1, 2);
        if (tig == 0) {
            int rg = lane >> 2;                    // 0..7
            int nq = warp >> 2;                    // 0..3
            red_s[nq][m_base + rg]     = a0;
            red_s[nq][m_base + 8 + rg] = a1;
        }
    }
    __syncthreads();

    // ---- softmax + outputs: warp w (0-1) handles node w
    if (warp < NPB) {
        const int j = lane;
        const int node = blockIdx.x * NPB + warp;
        float mlp = red_s[0][warp * 32 + j] + red_s[1][warp * 32 + j]
                  + red_s[2][warp * 32 + j] + red_s[3][warp * 32 + j] + b3[0];
        int cj = cjs_s[warp * 32 + j];

        float a = b_scal[0] * fabsf(mlp);
        float amax = a;
        #pragma unroll
        for (int o = 16; o > 0; o >>= 1)
            amax = fmaxf(amax, __shfl_xor_sync(0xffffffffu, amax, o));
        float e = __expf(a - amax);
        float esum = e;
        #pragma unroll
        for (int o = 16; o > 0; o >>= 1)
            esum += __shfl_xor_sync(0xffffffffu, esum, o);
        float wgt = mlp * (e / esum);

        float prop = t_arr[cj] - e_hat[cj];
        float yp = prop * wgt;
        #pragma unroll
        for (int o = 16; o > 0; o >>= 1)
            yp += __shfl_xor_sync(0xffffffffu, yp, o);
        if (lane == 0) ypred[node] = yp;

        // serial scatter (ascending j, last write wins)
        float* prow = pairwise + (size_t)node * N_NODES;
        #pragma unroll
        for (int jj = 0; jj < K_NB; jj++) {
            float wj = __shfl_sync(0xffffffffu, wgt, jj);
            int  cjj = __shfl_sync(0xffffffffu, cj,  jj);
            if (lane == 0) prow[cjj] = wj;
        }
        if (lane == 0) prow[node] = 0.f;
    }
}

// ---------------------------------------------------------------------------
extern "C" void kernel_launch(void* const* d_in, const int* in_sizes, int n_in,
                              void* d_out, int out_size) {
    const float* x     = (const float*)d_in[0];
    const int*   nbrs  = (const int*)  d_in[1];
    const float* t_arr = (const float*)d_in[2];
    const float* e_hat = (const float*)d_in[3];
    const float* W1    = (const float*)d_in[4];
    const float* b1    = (const float*)d_in[5];
    const float* W2    = (const float*)d_in[6];
    const float* b2    = (const float*)d_in[7];
    const float* W3    = (const float*)d_in[8];
    const float* b3    = (const float*)d_in[9];
    const float* bsc   = (const float*)d_in[10];

    float* ypred    = (float*)d_out;
    float* pairwise = ypred + N_NODES;

    static int smem_set = 0;
    if (!smem_set) {
        cudaFuncSetAttribute(mlp_kernel,
                             cudaFuncAttributeMaxDynamicSharedMemorySize,
                             SMEM_DYN);
        smem_set = 1;
    }

    int n4 = out_size / 4;
    zero_kernel<<<8192, 256>>>((float4*)d_out, n4);
    pq_kernel<<<N_NODES / ROWS_PER_BLK, 256>>>(x, W1, b1);
    w2prep_kernel<<<H_DIM, 256>>>(W2);
    mlp_kernel<<<N_NODES / NPB, THREADS, SMEM_DYN>>>(nbrs, t_arr, e_hat, b2, W3,
                                                     b3, bsc, ypred, pairwise);
}

// round 12
// speedup vs baseline: 1.2061x; 1.2061x over previous
#include <cuda_runtime.h>
#include <cuda_fp16.h>
#include <cstdint>
#include <stdint.h>
#include <math.h>

#define N_NODES 8192
#define K_NB    32
#define D_DIM   128
#define H_DIM   256
#define NGROUPS 4096     // node pairs (2 nodes per group, M = 64 rows)
#define MAXG    28

typedef unsigned int       u32;
typedef unsigned long long u64;

__device__ float g_P[N_NODES * H_DIM];   // x @ W1[:128] + b1
__device__ float g_Q[N_NODES * H_DIM];   // x @ W1[128:]
// W2^T fp16 swizzled smem image: row n (512B = 256 k), 128KB
__device__ __align__(16) unsigned char g_W2h[131072];

// ---------------- helpers ----------------
__device__ __forceinline__ u32 smem_u32(const void* p) {
    return (u32)__cvta_generic_to_shared(p);
}
__device__ __forceinline__ void cp_async16(u32 saddr, const void* gaddr) {
    asm volatile("cp.async.cg.shared.global [%0], [%1], 16;" :: "r"(saddr), "l"(gaddr));
}
__device__ __forceinline__ void cp_commit() { asm volatile("cp.async.commit_group;"); }
__device__ __forceinline__ void cp_wait0() {
    asm volatile("cp.async.wait_group 0;" ::: "memory");
}
__device__ __forceinline__ void ldsm4(u32* r, u32 addr) {
    asm volatile("ldmatrix.sync.aligned.m8n8.x4.shared.b16 {%0,%1,%2,%3}, [%4];"
                 : "=r"(r[0]), "=r"(r[1]), "=r"(r[2]), "=r"(r[3]) : "r"(addr));
}
__device__ __forceinline__ void mma_f16(float* c, const u32* a, const u32* b) {
    asm volatile(
        "mma.sync.aligned.m16n8k16.row.col.f32.f16.f16.f32 "
        "{%0,%1,%2,%3}, {%4,%5,%6,%7}, {%8,%9}, {%0,%1,%2,%3};"
        : "+f"(c[0]), "+f"(c[1]), "+f"(c[2]), "+f"(c[3])
        : "r"(a[0]), "r"(a[1]), "r"(a[2]), "r"(a[3]), "r"(b[0]), "r"(b[1]));
}

// build 64 k-values (hi/lo fp16) for one h1 row slice and store swizzled
__device__ __forceinline__ void build_slice(
    const float4* qv, const float* Pn, int ks, int row,
    unsigned char* h1hi_p, unsigned char* h1lo_p)
{
    const float4* pp = (const float4*)(Pn + ks);
    const u32 swz = (u32)((row & 7) << 4);
    const u32 rb  = (u32)(row * 512);
    #pragma unroll
    for (int c = 0; c < 8; c++) {
        float4 q0 = qv[2 * c], q1 = qv[2 * c + 1];
        float4 p0 = pp[2 * c], p1 = pp[2 * c + 1];
        float v0 = fmaxf(p0.x + q0.x, 0.f), v1 = fmaxf(p0.y + q0.y, 0.f);
        float v2 = fmaxf(p0.z + q0.z, 0.f), v3 = fmaxf(p0.w + q0.w, 0.f);
        float v4 = fmaxf(p1.x + q1.x, 0.f), v5 = fmaxf(p1.y + q1.y, 0.f);
        float v6 = fmaxf(p1.z + q1.z, 0.f), v7 = fmaxf(p1.w + q1.w, 0.f);
        __half2 h01 = __floats2half2_rn(v0, v1);
        __half2 h23 = __floats2half2_rn(v2, v3);
        __half2 h45 = __floats2half2_rn(v4, v5);
        __half2 h67 = __floats2half2_rn(v6, v7);
        __half2 l01 = __floats2half2_rn(v0 - __half2float(h01.x),
                                        v1 - __half2float(h01.y));
        __half2 l23 = __floats2half2_rn(v2 - __half2float(h23.x),
                                        v3 - __half2float(h23.y));
        __half2 l45 = __floats2half2_rn(v4 - __half2float(h45.x),
                                        v5 - __half2float(h45.y));
        __half2 l67 = __floats2half2_rn(v6 - __half2float(h67.x),
                                        v7 - __half2float(h67.y));
        uint4 hi4, lo4;
        hi4.x = *(u32*)&h01; hi4.y = *(u32*)&h23;
        hi4.z = *(u32*)&h45; hi4.w = *(u32*)&h67;
        lo4.x = *(u32*)&l01; lo4.y = *(u32*)&l23;
        lo4.z = *(u32*)&l45; lo4.w = *(u32*)&l67;
        u32 off = (rb + (u32)(((ks >> 3) + c) * 16)) ^ swz;
        *(uint4*)(h1hi_p + off) = hi4;
        *(uint4*)(h1lo_p + off) = lo4;
    }
}

// ---------------------------------------------------------------------------
#define ROWS_PER_BLK 16
__global__ __launch_bounds__(256) void pq_kernel(
    const float* __restrict__ x, const float* __restrict__ W1,
    const float* __restrict__ b1)
{
    __shared__ float xs[ROWS_PER_BLK * D_DIM];
    const int t = threadIdx.x;
    const int row0 = blockIdx.x * ROWS_PER_BLK;

    const float4* xsrc = (const float4*)(x + (size_t)row0 * D_DIM);
    float4* xdst = (float4*)xs;
    #pragma unroll
    for (int i = 0; i < (ROWS_PER_BLK * D_DIM / 4) / 256; i++)
        xdst[t + i * 256] = xsrc[t + i * 256];
    __syncthreads();

    float accP[ROWS_PER_BLK], accQ[ROWS_PER_BLK];
    #pragma unroll
    for (int r = 0; r < ROWS_PER_BLK; r++) { accP[r] = 0.f; accQ[r] = 0.f; }

    #pragma unroll 4
    for (int d = 0; d < D_DIM; d++) {
        float wp = W1[d * H_DIM + t];
        float wq = W1[(D_DIM + d) * H_DIM + t];
        #pragma unroll
        for (int r = 0; r < ROWS_PER_BLK; r++) {
            float xv = xs[r * D_DIM + d];
            accP[r] = fmaf(xv, wp, accP[r]);
            accQ[r] = fmaf(xv, wq, accQ[r]);
        }
    }
    float bb = b1[t];
    #pragma unroll
    for (int r = 0; r < ROWS_PER_BLK; r++) {
        g_P[(size_t)(row0 + r) * H_DIM + t] = accP[r] + bb;
        g_Q[(size_t)(row0 + r) * H_DIM + t] = accQ[r];
    }
}

// ---------------------------------------------------------------------------
__global__ void w2prep_kernel(const float* __restrict__ W2) {
    const int k = blockIdx.x;      // 0..255
    const int n = threadIdx.x;     // 0..255
    float v = W2[k * H_DIM + n];
    __half h = __float2half(v);
    u32 off = (u32)(n * 512 + k * 2) ^ (u32)((n & 7) << 4);
    *(__half*)&g_W2h[off] = h;
}

// ---------------------------------------------------------------------------
// Persistent main kernel: one CTA per SM, 256 threads (8 warps).
// smem: W2 fp16 (128KB) + h1 hi/lo (64KB) + P stage (4KB) = 200704 dyn.
// Each CTA loops over node-pair groups (stride gridDim.x). Per group:
//  top: prefetch next group's Q (regs) + P (cp.async), zero pairwise rows
//  MMA (warp tile 32x64, merged hi/lo accumulators)
//  fold -> red_s, sync, convert next h1, warp0/1 softmax+scatter, sync.
// ---------------------------------------------------------------------------
#define SMEM_DYN (131072 + 65536 + 4096)

__global__ __launch_bounds__(256, 1) void mlp_kernel(
    const int* __restrict__ nbrs,
    const float* __restrict__ t_arr, const float* __restrict__ e_hat,
    const float* __restrict__ b2, const float* __restrict__ W3,
    const float* __restrict__ b3, const float* __restrict__ b_scal,
    float* __restrict__ ypred, float* __restrict__ pairwise)
{
    extern __shared__ __align__(128) unsigned char dsm[];
    unsigned char* w2s_p  = dsm;             // 128KB
    unsigned char* h1hi_p = dsm + 131072;    // 32KB
    unsigned char* h1lo_p = dsm + 163840;    // 32KB
    float*         P_s    = (float*)(dsm + 196608);  // 2 bufs x 512 floats
    __shared__ int   cjs_all[MAXG * 64];
    __shared__ float red_s[4][64];
    __shared__ float b2s[H_DIM], w3s[H_DIM];

    const int tid  = threadIdx.x;
    const int lane = tid & 31;
    const int warp = tid >> 5;
    const int bid  = blockIdx.x;
    const int grid = gridDim.x;

    b2s[tid] = b2[tid];
    w3s[tid] = W3[tid];

    const u32 w2sa = smem_u32(w2s_p);
    const u32 h1hi = smem_u32(h1hi_p);
    const u32 h1lo = smem_u32(h1lo_p);
    const u32 psb  = smem_u32(P_s);

    // load full W2 image once (128KB; 512B per thread)
    #pragma unroll
    for (int t = 0; t < 32; t++) {
        int idx = (t * 256 + tid) * 16;
        cp_async16(w2sa + idx, g_W2h + idx);
    }
    cp_commit();

    // load all this CTA's neighbor indices once
    #pragma unroll
    for (int i = 0; i < 7; i++) {
        int idx = i * 256 + tid;
        int g8 = idx >> 6;
        int gp = bid + g8 * grid;
        if (idx < MAXG * 64 && gp < NGROUPS)
            cjs_all[idx] = nbrs[(2 * gp + ((idx >> 5) & 1)) * (K_NB + 1) + 1 + (idx & 31)];
    }

    // stage P for group 0 into P_s buf 0
    if (tid < 128) {
        int nn = 2 * bid + (tid >> 6);
        *(float4*)(P_s + tid * 4) =
            *(const float4*)(g_P + (size_t)nn * H_DIM + (tid & 63) * 4);
    }
    __syncthreads();   // cjs_all, P_s[0], b2s/w3s ready

    const int row = tid >> 2, kq = tid & 3, ks = kq * 64;

    // build h1 for group 0
    {
        int cj = cjs_all[row];
        float4 qv0[16];
        const float4* Qp = (const float4*)(g_Q + (size_t)cj * H_DIM) + (ks >> 2);
        #pragma unroll
        for (int i = 0; i < 16; i++) qv0[i] = Qp[i];
        build_slice(qv0, P_s + (row >> 5) * 256, ks, row, h1hi_p, h1lo_p);
    }
    cp_wait0();
    __syncthreads();   // h1 group 0 + W2 visible

    // ---- MMA geometry: warp&1 -> 32-row half, warp>>1 -> 64-col quarter
    const int m_base = (warp & 1) * 32;
    const int n_base = (warp >> 1) * 64;
    const int kbA = (lane >> 4) * 8;
    const int nB7  = (lane & 7) + ((lane >> 4) & 1) * 8;
    const int kkB7 = ((lane >> 3) & 1) * 8;
    const int tig  = lane & 3;
    const int mA0 = m_base + ((lane >> 3) & 1) * 8 + (lane & 7);

    #pragma unroll 1
    for (int g = 0;; g++) {
        int gp = bid + g * grid;
        if (gp >= NGROUPS) break;
        int gpn = gp + grid;
        bool has_next = (gpn < NGROUPS);

        // ---- prefetch next group: P via cp.async, Q into registers
        float4 qv[16];
        if (has_next) {
            if (tid < 128) {
                int nn = 2 * gpn + (tid >> 6);
                cp_async16(psb + (u32)(((g + 1) & 1) * 2048 + tid * 16),
                           g_P + (size_t)nn * H_DIM + (tid & 63) * 4);
            }
            int cjn = cjs_all[(g + 1) * 64 + row];
            const float4* Qp = (const float4*)(g_Q + (size_t)cjn * H_DIM) + (ks >> 2);
            #pragma unroll
            for (int i = 0; i < 16; i++) qv[i] = Qp[i];
        }
        cp_commit();

        // ---- zero this group's pairwise rows (2 rows x 32KB)
        {
            float4 z = make_float4(0.f, 0.f, 0.f, 0.f);
            float4* b4 = (float4*)(pairwise + (size_t)gp * 2 * N_NODES);
            #pragma unroll
            for (int v = 0; v < 16; v++) b4[v * 256 + tid] = z;
        }

        // ---- MMA mainloop (merged hi/lo accumulators)
        float cc[64];
        #pragma unroll
        for (int i = 0; i < 64; i++) cc[i] = 0.f;

        #pragma unroll 2
        for (int kt = 0; kt < 16; kt++) {
            u32 ah[2][4], al[2][4], bv[4][4];
            #pragma unroll
            for (int fm = 0; fm < 2; fm++) {
                int mA = mA0 + fm * 16;
                u32 offA = ((u32)(mA * 512 + (kt * 16 + kbA) * 2)) ^ (u32)((mA & 7) << 4);
                ldsm4(ah[fm], h1hi + offA);
                ldsm4(al[fm], h1lo + offA);
            }
            #pragma unroll
            for (int fb = 0; fb < 4; fb++) {
                int nB = n_base + fb * 16 + nB7;
                u32 offB = ((u32)(nB * 512 + (kt * 16 + kkB7) * 2)) ^ (u32)((nB & 7) << 4);
                ldsm4(bv[fb], w2sa + offB);
            }
            #pragma unroll
            for (int fm = 0; fm < 2; fm++)
                #pragma unroll
                for (int fb = 0; fb < 4; fb++) {
                    mma_f16(cc + (fm * 8 + 2 * fb) * 4,     ah[fm], bv[fb]);
                    mma_f16(cc + (fm * 8 + 2 * fb + 1) * 4, ah[fm], bv[fb] + 2);
                }
            #pragma unroll
            for (int fm = 0; fm < 2; fm++)
                #pragma unroll
                for (int fb = 0; fb < 4; fb++) {
                    mma_f16(cc + (fm * 8 + 2 * fb) * 4,     al[fm], bv[fb]);
                    mma_f16(cc + (fm * 8 + 2 * fb + 1) * 4, al[fm], bv[fb] + 2);
                }
        }

        // ---- fold relu(C + b2) . W3 per row
        {
            float a0 = 0.f, a1 = 0.f, a2 = 0.f, a3 = 0.f;
            #pragma unroll
            for (int fm = 0; fm < 2; fm++) {
                #pragma unroll
                for (int fn = 0; fn < 8; fn++) {
                    int col = n_base + fn * 8 + 2 * tig;
                    float b0 = b2s[col], b1v = b2s[col + 1];
                    float w0 = w3s[col], w1v = w3s[col + 1];
                    const float* cf = cc + (fm * 8 + fn) * 4;
                    float s0 = fmaf(fmaxf(cf[0] + b0, 0.f), w0,
                                    fmaxf(cf[1] + b1v, 0.f) * w1v);
                    float s1 = fmaf(fmaxf(cf[2] + b0, 0.f), w0,
                                    fmaxf(cf[3] + b1v, 0.f) * w1v);
                    if (fm == 0) { a0 += s0; a1 += s1; }
                    else         { a2 += s0; a3 += s1; }
                }
            }
            a0 += __shfl_xor_sync(0xffffffffu, a0, 1);
            a0 += __shfl_xor_sync(0xffffffffu, a0, 2);
            a1 += __shfl_xor_sync(0xffffffffu, a1, 1);
            a1 += __shfl_xor_sync(0xffffffffu, a1, 2);
            a2 += __shfl_xor_sync(0xffffffffu, a2, 1);
            a2 += __shfl_xor_sync(0xffffffffu, a2, 2);
            a3 += __shfl_xor_sync(0xffffffffu, a3, 1);
            a3 += __shfl_xor_sync(0xffffffffu, a3, 2);
            if (tig == 0) {
                int rg = lane >> 2;
                int nq = warp >> 1;
                red_s[nq][m_base + rg]      = a0;
                red_s[nq][m_base + 8 + rg]  = a1;
                red_s[nq][m_base + 16 + rg] = a2;
                red_s[nq][m_base + 24 + rg] = a3;
            }
        }
        cp_wait0();          // next-group P staged
        __syncthreads();     // MMA reads done, red_s + P_s visible

        // ---- build next group's h1 (overlaps with warp0/1 epilogue)
        if (has_next)
            build_slice(qv, P_s + ((g + 1) & 1) * 512 + (row >> 5) * 256,
                        ks, row, h1hi_p, h1lo_p);

        // ---- softmax + outputs: warp w (0-1) handles node 2*gp+w
        if (warp < 2) {
            const int j = lane;
            const int node = 2 * gp + warp;
            float mlp = red_s[0][warp * 32 + j] + red_s[1][warp * 32 + j]
                      + red_s[2][warp * 32 + j] + red_s[3][warp * 32 + j] + b3[0];
            int cj = cjs_all[g * 64 + warp * 32 + j];

            float a = b_scal[0] * fabsf(mlp);
            float amax = a;
            #pragma unroll
            for (int o = 16; o > 0; o >>= 1)
                amax = fmaxf(amax, __shfl_xor_sync(0xffffffffu, amax, o));
            float e = __expf(a - amax);
            float esum = e;
            #pragma unroll
            for (int o = 16; o > 0; o >>= 1)
                esum += __shfl_xor_sync(0xffffffffu, esum, o);
            float wgt = mlp * (e / esum);

            float prop = t_arr[cj] - e_hat[cj];
            float yp = prop * wgt;
            #pragma unroll
            for (int o = 16; o > 0; o >>= 1)
                yp += __shfl_xor_sync(0xffffffffu, yp, o);
            if (lane == 0) ypred[node] = yp;

            // serial scatter (ascending j, last write wins)
            float* prow = pairwise + (size_t)node * N_NODES;
            #pragma unroll
            for (int jj = 0; jj < K_NB; jj++) {
                float wj = __shfl_sync(0xffffffffu, wgt, jj);
                int  cjj = __shfl_sync(0xffffffffu, cj,  jj);
                if (lane == 0) prow[cjj] = wj;
            }
            if (lane == 0) prow[node] = 0.f;
        }
        __syncthreads();     // h1 for next group ready; scatter ordered
    }
}

// ---------------------------------------------------------------------------
extern "C" void kernel_launch(void* const* d_in, const int* in_sizes, int n_in,
                              void* d_out, int out_size) {
    const float* x     = (const float*)d_in[0];
    const int*   nbrs  = (const int*)  d_in[1];
    const float* t_arr = (const float*)d_in[2];
    const float* e_hat = (const float*)d_in[3];
    const float* W1    = (const float*)d_in[4];
    const float* b1    = (const float*)d_in[5];
    const float* W2    = (const float*)d_in[6];
    const float* b2    = (const float*)d_in[7];
    const float* W3    = (const float*)d_in[8];
    const float* b3    = (const float*)d_in[9];
    const float* bsc   = (const float*)d_in[10];

    float* ypred    = (float*)d_out;
    float* pairwise = ypred + N_NODES;

    static int nsm = 0;
    if (!nsm) {
        cudaDeviceProp prop;
        cudaGetDeviceProperties(&prop, 0);
        nsm = prop.multiProcessorCount;
        if (nsm < 1) nsm = 148;
        cudaFuncSetAttribute(mlp_kernel,
                             cudaFuncAttributeMaxDynamicSharedMemorySize,
                             SMEM_DYN);
    }

    pq_kernel<<<N_NODES / ROWS_PER_BLK, 256>>>(x, W1, b1);
    w2prep_kernel<<<H_DIM, 256>>>(W2);
    mlp_kernel<<<nsm, 256, SMEM_DYN>>>(nbrs, t_arr, e_hat, b2, W3,
                                       b3, bsc, ypred, pairwise);
}

// round 13
// speedup vs baseline: 1.7593x; 1.4587x over previous
#include <cuda_runtime.h>
#include <cuda_fp16.h>
#include <cstdint>
#include <stdint.h>
#include <math.h>

#define N_NODES 8192
#define K_NB    32
#define D_DIM   128
#define H_DIM   256
#define NGROUPS 4096     // node pairs (2 nodes per group, M = 64 rows)
#define MAXG    28

typedef unsigned int       u32;
typedef unsigned long long u64;

__device__ float g_P[N_NODES * H_DIM];   // x @ W1[:128] + b1
__device__ float g_Q[N_NODES * H_DIM];   // x @ W1[128:]
// W2^T fp16 swizzled smem image: row n (512B = 256 k), 128KB
__device__ __align__(16) unsigned char g_W2h[131072];

// ---------------- helpers ----------------
__device__ __forceinline__ u32 smem_u32(const void* p) {
    return (u32)__cvta_generic_to_shared(p);
}
__device__ __forceinline__ void cp_async16(u32 saddr, const void* gaddr) {
    asm volatile("cp.async.cg.shared.global [%0], [%1], 16;" :: "r"(saddr), "l"(gaddr));
}
__device__ __forceinline__ void cp_commit() { asm volatile("cp.async.commit_group;"); }
__device__ __forceinline__ void cp_wait0() {
    asm volatile("cp.async.wait_group 0;" ::: "memory");
}
__device__ __forceinline__ void ldsm4(u32* r, u32 addr) {
    asm volatile("ldmatrix.sync.aligned.m8n8.x4.shared.b16 {%0,%1,%2,%3}, [%4];"
                 : "=r"(r[0]), "=r"(r[1]), "=r"(r[2]), "=r"(r[3]) : "r"(addr));
}
__device__ __forceinline__ void mma_f16(float* c, const u32* a, const u32* b) {
    asm volatile(
        "mma.sync.aligned.m16n8k16.row.col.f32.f16.f16.f32 "
        "{%0,%1,%2,%3}, {%4,%5,%6,%7}, {%8,%9}, {%0,%1,%2,%3};"
        : "+f"(c[0]), "+f"(c[1]), "+f"(c[2]), "+f"(c[3])
        : "r"(a[0]), "r"(a[1]), "r"(a[2]), "r"(a[3]), "r"(b[0]), "r"(b[1]));
}

// build 64 k-values (single fp16) for one h1 row slice, store swizzled
__device__ __forceinline__ void build_slice(
    const float4* qv, const float* Pn, int ks, int row,
    unsigned char* h1_p)
{
    const float4* pp = (const float4*)(Pn + ks);
    const u32 swz = (u32)((row & 7) << 4);
    const u32 rb  = (u32)(row * 512);
    #pragma unroll
    for (int c = 0; c < 8; c++) {
        float4 q0 = qv[2 * c], q1 = qv[2 * c + 1];
        float4 p0 = pp[2 * c], p1 = pp[2 * c + 1];
        float v0 = fmaxf(p0.x + q0.x, 0.f), v1 = fmaxf(p0.y + q0.y, 0.f);
        float v2 = fmaxf(p0.z + q0.z, 0.f), v3 = fmaxf(p0.w + q0.w, 0.f);
        float v4 = fmaxf(p1.x + q1.x, 0.f), v5 = fmaxf(p1.y + q1.y, 0.f);
        float v6 = fmaxf(p1.z + q1.z, 0.f), v7 = fmaxf(p1.w + q1.w, 0.f);
        __half2 h01 = __floats2half2_rn(v0, v1);
        __half2 h23 = __floats2half2_rn(v2, v3);
        __half2 h45 = __floats2half2_rn(v4, v5);
        __half2 h67 = __floats2half2_rn(v6, v7);
        uint4 hi4;
        hi4.x = *(u32*)&h01; hi4.y = *(u32*)&h23;
        hi4.z = *(u32*)&h45; hi4.w = *(u32*)&h67;
        u32 off = (rb + (u32)(((ks >> 3) + c) * 16)) ^ swz;
        *(uint4*)(h1_p + off) = hi4;
    }
}

// ---------------------------------------------------------------------------
// PQ precompute, 32 rows/block (halves W1 L2 traffic vs 16).
// ---------------------------------------------------------------------------
#define ROWS_PER_BLK 32
__global__ __launch_bounds__(256) void pq_kernel(
    const float* __restrict__ x, const float* __restrict__ W1,
    const float* __restrict__ b1)
{
    __shared__ float xs[ROWS_PER_BLK * D_DIM];
    const int t = threadIdx.x;
    const int row0 = blockIdx.x * ROWS_PER_BLK;

    const float4* xsrc = (const float4*)(x + (size_t)row0 * D_DIM);
    float4* xdst = (float4*)xs;
    #pragma unroll
    for (int i = 0; i < (ROWS_PER_BLK * D_DIM / 4) / 256; i++)
        xdst[t + i * 256] = xsrc[t + i * 256];
    __syncthreads();

    float accP[ROWS_PER_BLK], accQ[ROWS_PER_BLK];
    #pragma unroll
    for (int r = 0; r < ROWS_PER_BLK; r++) { accP[r] = 0.f; accQ[r] = 0.f; }

    #pragma unroll 2
    for (int d = 0; d < D_DIM; d++) {
        float wp = W1[d * H_DIM + t];
        float wq = W1[(D_DIM + d) * H_DIM + t];
        #pragma unroll
        for (int r = 0; r < ROWS_PER_BLK; r++) {
            float xv = xs[r * D_DIM + d];
            accP[r] = fmaf(xv, wp, accP[r]);
            accQ[r] = fmaf(xv, wq, accQ[r]);
        }
    }
    float bb = b1[t];
    #pragma unroll
    for (int r = 0; r < ROWS_PER_BLK; r++) {
        g_P[(size_t)(row0 + r) * H_DIM + t] = accP[r] + bb;
        g_Q[(size_t)(row0 + r) * H_DIM + t] = accQ[r];
    }
}

// ---------------------------------------------------------------------------
__global__ void w2prep_kernel(const float* __restrict__ W2) {
    const int k = blockIdx.x;      // 0..255
    const int n = threadIdx.x;     // 0..255
    float v = W2[k * H_DIM + n];
    __half h = __float2half(v);
    u32 off = (u32)(n * 512 + k * 2) ^ (u32)((n & 7) << 4);
    *(__half*)&g_W2h[off] = h;
}

// ---------------------------------------------------------------------------
// Persistent main kernel: one CTA per SM, 256 threads (8 warps).
// smem: W2 fp16 (128KB) + h1 (32KB) + P stage (4KB) = 167936 dyn.
// Single-term fp16 MMA (A fp16, B fp16): 2048 MMAs per group.
// ---------------------------------------------------------------------------
#define SMEM_DYN (131072 + 32768 + 4096)

__global__ __launch_bounds__(256, 1) void mlp_kernel(
    const int* __restrict__ nbrs,
    const float* __restrict__ t_arr, const float* __restrict__ e_hat,
    const float* __restrict__ b2, const float* __restrict__ W3,
    const float* __restrict__ b3, const float* __restrict__ b_scal,
    float* __restrict__ ypred, float* __restrict__ pairwise)
{
    extern __shared__ __align__(128) unsigned char dsm[];
    unsigned char* w2s_p = dsm;             // 128KB
    unsigned char* h1_p  = dsm + 131072;    // 32KB
    float*         P_s   = (float*)(dsm + 163840);  // 2 bufs x 512 floats
    __shared__ int   cjs_all[MAXG * 64];
    __shared__ float red_s[4][64];
    __shared__ float b2s[H_DIM], w3s[H_DIM];

    const int tid  = threadIdx.x;
    const int lane = tid & 31;
    const int warp = tid >> 5;
    const int bid  = blockIdx.x;
    const int grid = gridDim.x;

    b2s[tid] = b2[tid];
    w3s[tid] = W3[tid];

    const u32 w2sa = smem_u32(w2s_p);
    const u32 h1sa = smem_u32(h1_p);
    const u32 psb  = smem_u32(P_s);

    // load full W2 image once (128KB; 512B per thread)
    #pragma unroll
    for (int t = 0; t < 32; t++) {
        int idx = (t * 256 + tid) * 16;
        cp_async16(w2sa + idx, g_W2h + idx);
    }
    cp_commit();

    // load all this CTA's neighbor indices once
    #pragma unroll
    for (int i = 0; i < 7; i++) {
        int idx = i * 256 + tid;
        int g8 = idx >> 6;
        int gp = bid + g8 * grid;
        if (idx < MAXG * 64 && gp < NGROUPS)
            cjs_all[idx] = nbrs[(2 * gp + ((idx >> 5) & 1)) * (K_NB + 1) + 1 + (idx & 31)];
    }

    // stage P for group 0 into P_s buf 0
    if (tid < 128) {
        int nn = 2 * bid + (tid >> 6);
        *(float4*)(P_s + tid * 4) =
            *(const float4*)(g_P + (size_t)nn * H_DIM + (tid & 63) * 4);
    }
    __syncthreads();   // cjs_all, P_s[0], b2s/w3s ready

    const int row = tid >> 2, kq = tid & 3, ks = kq * 64;

    // build h1 for group 0
    {
        int cj = cjs_all[row];
        float4 qv0[16];
        const float4* Qp = (const float4*)(g_Q + (size_t)cj * H_DIM) + (ks >> 2);
        #pragma unroll
        for (int i = 0; i < 16; i++) qv0[i] = Qp[i];
        build_slice(qv0, P_s + (row >> 5) * 256, ks, row, h1_p);
    }
    cp_wait0();
    __syncthreads();   // h1 group 0 + W2 visible

    // ---- MMA geometry: warp&1 -> 32-row half, warp>>1 -> 64-col quarter
    const int m_base = (warp & 1) * 32;
    const int n_base = (warp >> 1) * 64;
    const int kbA = (lane >> 4) * 8;
    const int nB7  = (lane & 7) + ((lane >> 4) & 1) * 8;
    const int kkB7 = ((lane >> 3) & 1) * 8;
    const int tig  = lane & 3;
    const int mA0 = m_base + ((lane >> 3) & 1) * 8 + (lane & 7);

    #pragma unroll 1
    for (int g = 0;; g++) {
        int gp = bid + g * grid;
        if (gp >= NGROUPS) break;
        int gpn = gp + grid;
        bool has_next = (gpn < NGROUPS);

        // ---- prefetch next group: P via cp.async, Q into registers
        float4 qv[16];
        if (has_next) {
            if (tid < 128) {
                int nn = 2 * gpn + (tid >> 6);
                cp_async16(psb + (u32)(((g + 1) & 1) * 2048 + tid * 16),
                           g_P + (size_t)nn * H_DIM + (tid & 63) * 4);
            }
            int cjn = cjs_all[(g + 1) * 64 + row];
            const float4* Qp = (const float4*)(g_Q + (size_t)cjn * H_DIM) + (ks >> 2);
            #pragma unroll
            for (int i = 0; i < 16; i++) qv[i] = Qp[i];
        }
        cp_commit();

        // ---- zero this group's pairwise rows (2 rows x 32KB)
        {
            float4 z = make_float4(0.f, 0.f, 0.f, 0.f);
            float4* b4 = (float4*)(pairwise + (size_t)gp * 2 * N_NODES);
            #pragma unroll
            for (int v = 0; v < 16; v++) b4[v * 256 + tid] = z;
        }

        // ---- MMA mainloop (single-term fp16)
        float cc[64];
        #pragma unroll
        for (int i = 0; i < 64; i++) cc[i] = 0.f;

        #pragma unroll 2
        for (int kt = 0; kt < 16; kt++) {
            u32 ah[2][4], bv[4][4];
            #pragma unroll
            for (int fm = 0; fm < 2; fm++) {
                int mA = mA0 + fm * 16;
                u32 offA = ((u32)(mA * 512 + (kt * 16 + kbA) * 2)) ^ (u32)((mA & 7) << 4);
                ldsm4(ah[fm], h1sa + offA);
            }
            #pragma unroll
            for (int fb = 0; fb < 4; fb++) {
                int nB = n_base + fb * 16 + nB7;
                u32 offB = ((u32)(nB * 512 + (kt * 16 + kkB7) * 2)) ^ (u32)((nB & 7) << 4);
                ldsm4(bv[fb], w2sa + offB);
            }
            #pragma unroll
            for (int fm = 0; fm < 2; fm++)
                #pragma unroll
                for (int fb = 0; fb < 4; fb++) {
                    mma_f16(cc + (fm * 8 + 2 * fb) * 4,     ah[fm], bv[fb]);
                    mma_f16(cc + (fm * 8 + 2 * fb + 1) * 4, ah[fm], bv[fb] + 2);
                }
        }

        // ---- fold relu(C + b2) . W3 per row
        {
            float a0 = 0.f, a1 = 0.f, a2 = 0.f, a3 = 0.f;
            #pragma unroll
            for (int fm = 0; fm < 2; fm++) {
                #pragma unroll
                for (int fn = 0; fn < 8; fn++) {
                    int col = n_base + fn * 8 + 2 * tig;
                    float b0 = b2s[col], b1v = b2s[col + 1];
                    float w0 = w3s[col], w1v = w3s[col + 1];
                    const float* cf = cc + (fm * 8 + fn) * 4;
                    float s0 = fmaf(fmaxf(cf[0] + b0, 0.f), w0,
                                    fmaxf(cf[1] + b1v, 0.f) * w1v);
                    float s1 = fmaf(fmaxf(cf[2] + b0, 0.f), w0,
                                    fmaxf(cf[3] + b1v, 0.f) * w1v);
                    if (fm == 0) { a0 += s0; a1 += s1; }
                    else         { a2 += s0; a3 += s1; }
                }
            }
            a0 += __shfl_xor_sync(0xffffffffu, a0, 1);
            a0 += __shfl_xor_sync(0xffffffffu, a0, 2);
            a1 += __shfl_xor_sync(0xffffffffu, a1, 1);
            a1 += __shfl_xor_sync(0xffffffffu, a1, 2);
            a2 += __shfl_xor_sync(0xffffffffu, a2, 1);
            a2 += __shfl_xor_sync(0xffffffffu, a2, 2);
            a3 += __shfl_xor_sync(0xffffffffu, a3, 1);
            a3 += __shfl_xor_sync(0xffffffffu, a3, 2);
            if (tig == 0) {
                int rg = lane >> 2;
                int nq = warp >> 1;
                red_s[nq][m_base + rg]      = a0;
                red_s[nq][m_base + 8 + rg]  = a1;
                red_s[nq][m_base + 16 + rg] = a2;
                red_s[nq][m_base + 24 + rg] = a3;
            }
        }
        cp_wait0();          // next-group P staged
        __syncthreads();     // MMA reads done, red_s + P_s visible

        // ---- build next group's h1 (overlaps with warp0/1 epilogue)
        if (has_next)
            build_slice(qv, P_s + ((g + 1) & 1) * 512 + (row >> 5) * 256,
                        ks, row, h1_p);

        // ---- softmax + outputs: warp w (0-1) handles node 2*gp+w
        if (warp < 2) {
            const int j = lane;
            const int node = 2 * gp + warp;
            float mlp = red_s[0][warp * 32 + j] + red_s[1][warp * 32 + j]
                      + red_s[2][warp * 32 + j] + red_s[3][warp * 32 + j] + b3[0];
            int cj = cjs_all[g * 64 + warp * 32 + j];

            float a = b_scal[0] * fabsf(mlp);
            float amax = a;
            #pragma unroll
            for (int o = 16; o > 0; o >>= 1)
                amax = fmaxf(amax, __shfl_xor_sync(0xffffffffu, amax, o));
            float e = __expf(a - amax);
            float esum = e;
            #pragma unroll
            for (int o = 16; o > 0; o >>= 1)
                esum += __shfl_xor_sync(0xffffffffu, esum, o);
            float wgt = mlp * (e / esum);

            float prop = t_arr[cj] - e_hat[cj];
            float yp = prop * wgt;
            #pragma unroll
            for (int o = 16; o > 0; o >>= 1)
                yp += __shfl_xor_sync(0xffffffffu, yp, o);
            if (lane == 0) ypred[node] = yp;

            // serial scatter (ascending j, last write wins)
            float* prow = pairwise + (size_t)node * N_NODES;
            #pragma unroll
            for (int jj = 0; jj < K_NB; jj++) {
                float wj = __shfl_sync(0xffffffffu, wgt, jj);
                int  cjj = __shfl_sync(0xffffffffu, cj,  jj);
                if (lane == 0) prow[cjj] = wj;
            }
            if (lane == 0) prow[node] = 0.f;
        }
        __syncthreads();     // h1 for next group ready; scatter ordered
    }
}

// ---------------------------------------------------------------------------
extern "C" void kernel_launch(void* const* d_in, const int* in_sizes, int n_in,
                              void* d_out, int out_size) {
    const float* x     = (const float*)d_in[0];
    const int*   nbrs  = (const int*)  d_in[1];
    const float* t_arr = (const float*)d_in[2];
    const float* e_hat = (const float*)d_in[3];
    const float* W1    = (const float*)d_in[4];
    const float* b1    = (const float*)d_in[5];
    const float* W2    = (const float*)d_in[6];
    const float* b2    = (const float*)d_in[7];
    const float* W3    = (const float*)d_in[8];
    const float* b3    = (const float*)d_in[9];
    const float* bsc   = (const float*)d_in[10];

    float* ypred    = (float*)d_out;
    float* pairwise = ypred + N_NODES;

    static int nsm = 0;
    if (!nsm) {
        cudaDeviceProp prop;
        cudaGetDeviceProperties(&prop, 0);
        nsm = prop.multiProcessorCount;
        if (nsm < 1) nsm = 148;
        cudaFuncSetAttribute(mlp_kernel,
                             cudaFuncAttributeMaxDynamicSharedMemorySize,
                             SMEM_DYN);
    }

    pq_kernel<<<N_NODES / ROWS_PER_BLK, 256>>>(x, W1, b1);
    w2prep_kernel<<<H_DIM, 256>>>(W2);
    mlp_kernel<<<nsm, 256, SMEM_DYN>>>(nbrs, t_arr, e_hat, b2, W3,
                                       b3, bsc, ypred, pairwise);
}

// round 14
// speedup vs baseline: 1.8825x; 1.0700x over previous
#include <cuda_runtime.h>
#include <cuda_fp16.h>
#include <cstdint>
#include <stdint.h>
#include <math.h>

#define N_NODES 8192
#define K_NB    32
#define D_DIM   128
#define H_DIM   256
#define NGROUPS 4096     // node pairs (2 nodes per group, M = 64 rows)
#define MAXG    28

typedef unsigned int       u32;
typedef unsigned long long u64;

__device__ float g_P[N_NODES * H_DIM];   // x @ W1[:128] + b1
__device__ float g_Q[N_NODES * H_DIM];   // x @ W1[128:]
// W2^T fp16 swizzled smem image: row n (512B = 256 k), 128KB
__device__ __align__(16) unsigned char g_W2h[131072];

// ---------------- helpers ----------------
__device__ __forceinline__ u32 smem_u32(const void* p) {
    return (u32)__cvta_generic_to_shared(p);
}
__device__ __forceinline__ void cp_async16(u32 saddr, const void* gaddr) {
    asm volatile("cp.async.cg.shared.global [%0], [%1], 16;" :: "r"(saddr), "l"(gaddr));
}
__device__ __forceinline__ void cp_commit() { asm volatile("cp.async.commit_group;"); }
__device__ __forceinline__ void cp_wait0() {
    asm volatile("cp.async.wait_group 0;" ::: "memory");
}
__device__ __forceinline__ void ldsm4(u32* r, u32 addr) {
    asm volatile("ldmatrix.sync.aligned.m8n8.x4.shared.b16 {%0,%1,%2,%3}, [%4];"
                 : "=r"(r[0]), "=r"(r[1]), "=r"(r[2]), "=r"(r[3]) : "r"(addr));
}
__device__ __forceinline__ void mma_f16(float* c, const u32* a, const u32* b) {
    asm volatile(
        "mma.sync.aligned.m16n8k16.row.col.f32.f16.f16.f32 "
        "{%0,%1,%2,%3}, {%4,%5,%6,%7}, {%8,%9}, {%0,%1,%2,%3};"
        : "+f"(c[0]), "+f"(c[1]), "+f"(c[2]), "+f"(c[3])
        : "r"(a[0]), "r"(a[1]), "r"(a[2]), "r"(a[3]), "r"(b[0]), "r"(b[1]));
}

// build 64 k-values (fp16) for one h1 row slice; Q loaded here (LDG)
__device__ __forceinline__ void build_slice(
    const float* Qn, const float* Pn, int ks, int row,
    unsigned char* h1_p)
{
    const float4* qp = (const float4*)(Qn + ks);
    const float4* pp = (const float4*)(Pn + ks);
    float4 qv[16];
    #pragma unroll
    for (int i = 0; i < 16; i++) qv[i] = qp[i];
    const u32 swz = (u32)((row & 7) << 4);
    const u32 rb  = (u32)(row * 512);
    #pragma unroll
    for (int c = 0; c < 8; c++) {
        float4 q0 = qv[2 * c], q1 = qv[2 * c + 1];
        float4 p0 = pp[2 * c], p1 = pp[2 * c + 1];
        float v0 = fmaxf(p0.x + q0.x, 0.f), v1 = fmaxf(p0.y + q0.y, 0.f);
        float v2 = fmaxf(p0.z + q0.z, 0.f), v3 = fmaxf(p0.w + q0.w, 0.f);
        float v4 = fmaxf(p1.x + q1.x, 0.f), v5 = fmaxf(p1.y + q1.y, 0.f);
        float v6 = fmaxf(p1.z + q1.z, 0.f), v7 = fmaxf(p1.w + q1.w, 0.f);
        __half2 h01 = __floats2half2_rn(v0, v1);
        __half2 h23 = __floats2half2_rn(v2, v3);
        __half2 h45 = __floats2half2_rn(v4, v5);
        __half2 h67 = __floats2half2_rn(v6, v7);
        uint4 hi4;
        hi4.x = *(u32*)&h01; hi4.y = *(u32*)&h23;
        hi4.z = *(u32*)&h45; hi4.w = *(u32*)&h67;
        u32 off = (rb + (u32)(((ks >> 3) + c) * 16)) ^ swz;
        *(uint4*)(h1_p + off) = hi4;
    }
}

// ---------------------------------------------------------------------------
#define ROWS_PER_BLK 32
__global__ __launch_bounds__(256) void pq_kernel(
    const float* __restrict__ x, const float* __restrict__ W1,
    const float* __restrict__ b1)
{
    __shared__ float xs[ROWS_PER_BLK * D_DIM];
    const int t = threadIdx.x;
    const int row0 = blockIdx.x * ROWS_PER_BLK;

    const float4* xsrc = (const float4*)(x + (size_t)row0 * D_DIM);
    float4* xdst = (float4*)xs;
    #pragma unroll
    for (int i = 0; i < (ROWS_PER_BLK * D_DIM / 4) / 256; i++)
        xdst[t + i * 256] = xsrc[t + i * 256];
    __syncthreads();

    float accP[ROWS_PER_BLK], accQ[ROWS_PER_BLK];
    #pragma unroll
    for (int r = 0; r < ROWS_PER_BLK; r++) { accP[r] = 0.f; accQ[r] = 0.f; }

    #pragma unroll 2
    for (int d = 0; d < D_DIM; d++) {
        float wp = W1[d * H_DIM + t];
        float wq = W1[(D_DIM + d) * H_DIM + t];
        #pragma unroll
        for (int r = 0; r < ROWS_PER_BLK; r++) {
            float xv = xs[r * D_DIM + d];
            accP[r] = fmaf(xv, wp, accP[r]);
            accQ[r] = fmaf(xv, wq, accQ[r]);
        }
    }
    float bb = b1[t];
    #pragma unroll
    for (int r = 0; r < ROWS_PER_BLK; r++) {
        g_P[(size_t)(row0 + r) * H_DIM + t] = accP[r] + bb;
        g_Q[(size_t)(row0 + r) * H_DIM + t] = accQ[r];
    }
}

// ---------------------------------------------------------------------------
__global__ void w2prep_kernel(const float* __restrict__ W2) {
    const int k = blockIdx.x;      // 0..255
    const int n = threadIdx.x;     // 0..255
    float v = W2[k * H_DIM + n];
    __half h = __float2half(v);
    u32 off = (u32)(n * 512 + k * 2) ^ (u32)((n & 7) << 4);
    *(__half*)&g_W2h[off] = h;
}

// ---------------------------------------------------------------------------
// Persistent main kernel: one CTA per SM, 256 threads (8 warps).
// smem: W2 fp16 (128KB) + h1 double buffer (2x32KB) + P stage (4KB).
// ONE __syncthreads per group; epilogue (warps 0/1) overlaps next group's
// MMA (warps 2-7); scatter via __match_any_sync (last-wins = highest lane).
// ---------------------------------------------------------------------------
#define SMEM_DYN (131072 + 65536 + 4096)

__global__ __launch_bounds__(256, 1) void mlp_kernel(
    const int* __restrict__ nbrs,
    const float* __restrict__ t_arr, const float* __restrict__ e_hat,
    const float* __restrict__ b2, const float* __restrict__ W3,
    const float* __restrict__ b3, const float* __restrict__ b_scal,
    float* __restrict__ ypred, float* __restrict__ pairwise)
{
    extern __shared__ __align__(128) unsigned char dsm[];
    unsigned char* w2s_p = dsm;             // 128KB
    unsigned char* h1b_p = dsm + 131072;    // 2 x 32KB
    float*         P_s   = (float*)(dsm + 196608);  // 2 bufs x 512 floats
    __shared__ int   cjs_all[MAXG * 64];
    __shared__ float red_s[2][4][64];
    __shared__ float b2s[H_DIM], w3s[H_DIM];

    const int tid  = threadIdx.x;
    const int lane = tid & 31;
    const int warp = tid >> 5;
    const int bid  = blockIdx.x;
    const int grid = gridDim.x;

    b2s[tid] = b2[tid];
    w3s[tid] = W3[tid];

    const u32 w2sa  = smem_u32(w2s_p);
    const u32 h1sa0 = smem_u32(h1b_p);
    const u32 psb   = smem_u32(P_s);

    // load full W2 image once (128KB; 512B per thread)
    #pragma unroll
    for (int t = 0; t < 32; t++) {
        int idx = (t * 256 + tid) * 16;
        cp_async16(w2sa + idx, g_W2h + idx);
    }
    cp_commit();

    // load all this CTA's neighbor indices once
    #pragma unroll
    for (int i = 0; i < 7; i++) {
        int idx = i * 256 + tid;
        int g8 = idx >> 6;
        int gp = bid + g8 * grid;
        if (idx < MAXG * 64 && gp < NGROUPS)
            cjs_all[idx] = nbrs[(2 * gp + ((idx >> 5) & 1)) * (K_NB + 1) + 1 + (idx & 31)];
    }

    // stage P for group 0 into P_s buf 0
    if (tid < 128) {
        int nn = 2 * bid + (tid >> 6);
        *(float4*)(P_s + tid * 4) =
            *(const float4*)(g_P + (size_t)nn * H_DIM + (tid & 63) * 4);
    }
    __syncthreads();   // cjs_all, P_s[0], b2s/w3s ready

    const int row = tid >> 2, ks = (tid & 3) * 64;

    // build h1 for group 0 into buffer 0
    build_slice(g_Q + (size_t)cjs_all[row] * H_DIM,
                P_s + (row >> 5) * 256, ks, row, (unsigned char*)h1b_p);
    cp_wait0();
    __syncthreads();   // h1[0] + W2 visible

    // ---- MMA geometry: warp&1 -> 32-row half, warp>>1 -> 64-col quarter
    const int m_base = (warp & 1) * 32;
    const int n_base = (warp >> 1) * 64;
    const int kbA = (lane >> 4) * 8;
    const int nB7  = (lane & 7) + ((lane >> 4) & 1) * 8;
    const int kkB7 = ((lane >> 3) & 1) * 8;
    const int tig  = lane & 3;
    const int mA0 = m_base + ((lane >> 3) & 1) * 8 + (lane & 7);

    #pragma unroll 1
    for (int g = 0;; g++) {
        int gp = bid + g * grid;
        if (gp >= NGROUPS) break;
        int gpn = gp + grid;
        bool has_next = (gpn < NGROUPS);

        // ---- stage next group's P
        if (has_next && tid < 128) {
            int nn = 2 * gpn + (tid >> 6);
            cp_async16(psb + (u32)(((g + 1) & 1) * 2048 + tid * 16),
                       g_P + (size_t)nn * H_DIM + (tid & 63) * 4);
        }
        cp_commit();

        // ---- zero this group's pairwise rows (2 rows x 32KB)
        {
            float4 z = make_float4(0.f, 0.f, 0.f, 0.f);
            float4* b4 = (float4*)(pairwise + (size_t)gp * 2 * N_NODES);
            #pragma unroll
            for (int v = 0; v < 16; v++) b4[v * 256 + tid] = z;
        }

        // ---- MMA mainloop on h1[g&1]
        const u32 h1sa = h1sa0 + (u32)((g & 1) * 32768);
        float cc[64];
        #pragma unroll
        for (int i = 0; i < 64; i++) cc[i] = 0.f;

        #pragma unroll 2
        for (int kt = 0; kt < 16; kt++) {
            u32 ah[2][4], bv[4][4];
            #pragma unroll
            for (int fm = 0; fm < 2; fm++) {
                int mA = mA0 + fm * 16;
                u32 offA = ((u32)(mA * 512 + (kt * 16 + kbA) * 2)) ^ (u32)((mA & 7) << 4);
                ldsm4(ah[fm], h1sa + offA);
            }
            #pragma unroll
            for (int fb = 0; fb < 4; fb++) {
                int nB = n_base + fb * 16 + nB7;
                u32 offB = ((u32)(nB * 512 + (kt * 16 + kkB7) * 2)) ^ (u32)((nB & 7) << 4);
                ldsm4(bv[fb], w2sa + offB);
            }
            #pragma unroll
            for (int fm = 0; fm < 2; fm++)
                #pragma unroll
                for (int fb = 0; fb < 4; fb++) {
                    mma_f16(cc + (fm * 8 + 2 * fb) * 4,     ah[fm], bv[fb]);
                    mma_f16(cc + (fm * 8 + 2 * fb + 1) * 4, ah[fm], bv[fb] + 2);
                }
        }

        // ---- fold relu(C + b2) . W3 per row into red_s[g&1]
        {
            float a0 = 0.f, a1 = 0.f, a2 = 0.f, a3 = 0.f;
            #pragma unroll
            for (int fm = 0; fm < 2; fm++) {
                #pragma unroll
                for (int fn = 0; fn < 8; fn++) {
                    int col = n_base + fn * 8 + 2 * tig;
                    float b0 = b2s[col], b1v = b2s[col + 1];
                    float w0 = w3s[col], w1v = w3s[col + 1];
                    const float* cf = cc + (fm * 8 + fn) * 4;
                    float s0 = fmaf(fmaxf(cf[0] + b0, 0.f), w0,
                                    fmaxf(cf[1] + b1v, 0.f) * w1v);
                    float s1 = fmaf(fmaxf(cf[2] + b0, 0.f), w0,
                                    fmaxf(cf[3] + b1v, 0.f) * w1v);
                    if (fm == 0) { a0 += s0; a1 += s1; }
                    else         { a2 += s0; a3 += s1; }
                }
            }
            a0 += __shfl_xor_sync(0xffffffffu, a0, 1);
            a0 += __shfl_xor_sync(0xffffffffu, a0, 2);
            a1 += __shfl_xor_sync(0xffffffffu, a1, 1);
            a1 += __shfl_xor_sync(0xffffffffu, a1, 2);
            a2 += __shfl_xor_sync(0xffffffffu, a2, 1);
            a2 += __shfl_xor_sync(0xffffffffu, a2, 2);
            a3 += __shfl_xor_sync(0xffffffffu, a3, 1);
            a3 += __shfl_xor_sync(0xffffffffu, a3, 2);
            if (tig == 0) {
                int rg = lane >> 2;
                int nq = warp >> 1;
                float* rs = &red_s[g & 1][nq][0];
                rs[m_base + rg]      = a0;
                rs[m_base + 8 + rg]  = a1;
                rs[m_base + 16 + rg] = a2;
                rs[m_base + 24 + rg] = a3;
            }
        }

        // ---- build next group's h1 into buffer (g+1)&1
        if (has_next) {
            cp_wait0();    // next P staged
            build_slice(g_Q + (size_t)cjs_all[(g + 1) * 64 + row] * H_DIM,
                        P_s + ((g + 1) & 1) * 512 + (row >> 5) * 256, ks, row,
                        h1b_p + ((g + 1) & 1) * 32768);
        }

        __syncthreads();   // h1[(g+1)&1], red_s[g&1], zero-STGs all ordered

        // ---- epilogue: warps 0/1 handle node 2*gp+warp (overlaps next MMA)
        if (warp < 2) {
            const int j = lane;
            const int node = 2 * gp + warp;
            const float* rs0 = &red_s[g & 1][0][0];
            float mlp = rs0[warp * 32 + j] + rs0[64 + warp * 32 + j]
                      + rs0[128 + warp * 32 + j] + rs0[192 + warp * 32 + j] + b3[0];
            int cj = cjs_all[g * 64 + warp * 32 + j];

            float a = b_scal[0] * fabsf(mlp);
            float amax = a;
            #pragma unroll
            for (int o = 16; o > 0; o >>= 1)
                amax = fmaxf(amax, __shfl_xor_sync(0xffffffffu, amax, o));
            float e = __expf(a - amax);
            float esum = e;
            #pragma unroll
            for (int o = 16; o > 0; o >>= 1)
                esum += __shfl_xor_sync(0xffffffffu, esum, o);
            float wgt = mlp * (e / esum);

            float prop = t_arr[cj] - e_hat[cj];
            float yp = prop * wgt;
            #pragma unroll
            for (int o = 16; o > 0; o >>= 1)
                yp += __shfl_xor_sync(0xffffffffu, yp, o);
            if (lane == 0) ypred[node] = yp;

            // parallel scatter: last-wins = highest lane of each match group
            float* prow = pairwise + (size_t)node * N_NODES;
            u32 mk = __match_any_sync(0xffffffffu, cj);
            int leader = 31 - __clz(mk);
            if (lane == leader && cj != node) prow[cj] = wgt;
            if (lane == 0) prow[node] = 0.f;
        }
    }
}

// ---------------------------------------------------------------------------
extern "C" void kernel_launch(void* const* d_in, const int* in_sizes, int n_in,
                              void* d_out, int out_size) {
    const float* x     = (const float*)d_in[0];
    const int*   nbrs  = (const int*)  d_in[1];
    const float* t_arr = (const float*)d_in[2];
    const float* e_hat = (const float*)d_in[3];
    const float* W1    = (const float*)d_in[4];
    const float* b1    = (const float*)d_in[5];
    const float* W2    = (const float*)d_in[6];
    const float* b2    = (const float*)d_in[7];
    const float* W3    = (const float*)d_in[8];
    const float* b3    = (const float*)d_in[9];
    const float* bsc   = (const float*)d_in[10];

    float* ypred    = (float*)d_out;
    float* pairwise = ypred + N_NODES;

    static int nsm = 0;
    if (!nsm) {
        cudaDeviceProp prop;
        cudaGetDeviceProperties(&prop, 0);
        nsm = prop.multiProcessorCount;
        if (nsm < 1) nsm = 148;
        cudaFuncSetAttribute(mlp_kernel,
                             cudaFuncAttributeMaxDynamicSharedMemorySize,
                             SMEM_DYN);
    }

    pq_kernel<<<N_NODES / ROWS_PER_BLK, 256>>>(x, W1, b1);
    w2prep_kernel<<<H_DIM, 256>>>(W2);
    mlp_kernel<<<nsm, 256, SMEM_DYN>>>(nbrs, t_arr, e_hat, b2, W3,
                                       b3, bsc, ypred, pairwise);
}